// round 15
// baseline (speedup 1.0000x reference)
#include <cuda_runtime.h>
#include <cuda_bf16.h>
#include <cstdint>

#define BATCH      8192
#define IN_CAP_N   1152
#define OUT_CAP_N  55
#define F4_PER_K   288            // 1152/4 float4 per (b,i) row
#define CAP_BYTES  4608           // one capsule row: 288 * 16
#define ELEM_BYTES 23040          // 5 * 4608
#define A_BYTES    9216           // capsules 0-1
#define B_BYTES    13824          // capsules 2-4
#define WARPS      8
#define NCTA       148
#define NSTREAM    (NCTA * WARPS) // 1184 persistent warp-streams
#define DYN_SMEM   (WARPS * ELEM_BYTES)   // 184320 B, 1 CTA/SM

__device__ __forceinline__ uint32_t smem_u32(const void* p) {
    uint32_t a;
    asm("{ .reg .u64 t; cvta.to.shared.u64 t, %1; cvt.u32.u64 %0, t; }"
        : "=r"(a) : "l"(p));
    return a;
}
__device__ __forceinline__ void mbar_init(uint32_t mbar, uint32_t cnt) {
    asm volatile("mbarrier.init.shared.b64 [%0], %1;" :: "r"(mbar), "r"(cnt) : "memory");
}
__device__ __forceinline__ void mbar_expect_tx(uint32_t mbar, uint32_t bytes) {
    asm volatile("mbarrier.arrive.expect_tx.shared.b64 _, [%0], %1;"
                 :: "r"(mbar), "r"(bytes) : "memory");
}
__device__ __forceinline__ void mbar_wait(uint32_t mbar, uint32_t parity) {
    asm volatile(
        "{\n\t.reg .pred P;\n\t"
        "WL_%=:\n\t"
        "mbarrier.try_wait.parity.acquire.cta.shared::cta.b64 P, [%0], %1, 0x989680;\n\t"
        "@P bra WD_%=;\n\t"
        "bra WL_%=;\n\t"
        "WD_%=:\n\t}"
        :: "r"(mbar), "r"(parity) : "memory");
}
__device__ __forceinline__ void bulk_load(uint32_t dst_smem, const void* src_gmem,
                                          uint32_t bytes, uint32_t mbar) {
    asm volatile(
        "cp.async.bulk.shared::cta.global.mbarrier::complete_tx::bytes [%0], [%1], %2, [%3];"
        :: "r"(dst_smem), "l"(src_gmem), "r"(bytes), "r"(mbar) : "memory");
}

__global__ __launch_bounds__(256, 1) void digitcaps_kernel(
    const float4* __restrict__ u4,   // (B, 5, 1152) as float4
    const float4* __restrict__ w4,   // (1152,) as float4
    const float*  __restrict__ bvec, // (55,)
    float*        __restrict__ out)  // (B, 55)
{
    extern __shared__ __align__(1024) unsigned char dynbuf[];   // 8 slots * 23040
    __shared__ float4 ws[F4_PER_K];
    __shared__ __align__(8) unsigned long long mbar_store[WARPS * 2]; // [warp]={A,B}

    const int tid  = threadIdx.x;
    const int lane = tid & 31;
    const int warp = tid >> 5;

    for (int idx = tid; idx < F4_PER_K; idx += 256)
        ws[idx] = w4[idx];
    if (tid < WARPS * 2)
        mbar_init(smem_u32(&mbar_store[tid]), 1);
    __syncthreads();

    const int gw = blockIdx.x * WARPS + warp;   // 0..1183 warp-stream id
    unsigned char* mybuf = dynbuf + (size_t)warp * ELEM_BYTES;
    const uint32_t buf_u = smem_u32(mybuf);
    const uint32_t mbA   = smem_u32(&mbar_store[warp * 2 + 0]);
    const uint32_t mbB   = smem_u32(&mbar_store[warp * 2 + 1]);
    const char*    usrc  = (const char*)u4;

    // Prologue: load both halves of this stream's first element
    if (lane == 0) {
        const char* s0 = usrc + (size_t)gw * ELEM_BYTES;
        mbar_expect_tx(mbA, A_BYTES);
        bulk_load(buf_u, s0, A_BYTES, mbA);
        mbar_expect_tx(mbB, B_BYTES);
        bulk_load(buf_u + A_BYTES, s0 + A_BYTES, B_BYTES, mbB);
    }

    // Routing-invariant epilogue constants
    const int  o0   = lane;
    const int  o1   = lane + 32;
    const bool has1 = (o1 < OUT_CAP_N);
    const float base0 = bvec[o0];
    const float base1 = has1 ? bvec[o1] : 0.f;

    // Iteration-0 softmax depends only on bvec: hoist out of the element loop.
    float m0 = has1 ? fmaxf(base0, base1) : base0;
    #pragma unroll
    for (int off = 16; off > 0; off >>= 1)
        m0 = fmaxf(m0, __shfl_xor_sync(0xffffffffu, m0, off));
    const float e0w = __expf(base0 - m0);
    const float e1w = has1 ? __expf(base1 - m0) : 0.f;
    float d0 = e0w + e1w;
    #pragma unroll
    for (int off = 16; off > 0; off >>= 1)
        d0 += __shfl_xor_sync(0xffffffffu, d0, off);

    int k = 0;
    for (int n = gw; n < BATCH; n += NSTREAM, k++) {
        const uint32_t par  = (uint32_t)(k & 1);
        const bool     more = (n + NSTREAM < BATCH);
        const char*    nsrc = usrc + (size_t)(n + NSTREAM) * ELEM_BYTES;

        // ---- half A: capsules 0,1 ----
        mbar_wait(mbA, par);
        float acc[5];
        #pragma unroll
        for (int i = 0; i < 2; i++) {
            const float4* cp = (const float4*)(mybuf + i * CAP_BYTES);
            float a = 0.f;
            #pragma unroll
            for (int j = 0; j < 9; j++) {
                const float4 x = cp[j * 32 + lane];
                const float4 w = ws[j * 32 + lane];
                a = fmaf(x.x, w.x, fmaf(x.y, w.y, fmaf(x.z, w.z, fmaf(x.w, w.w, a))));
            }
            acc[i] = a;
        }
        // reduce A-accs first: SHFL reads force every lane's A-loads complete
        #pragma unroll
        for (int off = 16; off > 0; off >>= 1) {
            acc[0] += __shfl_xor_sync(0xffffffffu, acc[0], off);
            acc[1] += __shfl_xor_sync(0xffffffffu, acc[1], off);
        }
        __syncwarp();
        if (lane == 0 && more) {               // refill A with next element
            mbar_expect_tx(mbA, A_BYTES);
            bulk_load(buf_u, nsrc, A_BYTES, mbA);
        }

        // ---- half B: capsules 2,3,4 (overlaps A's in-flight refill) ----
        mbar_wait(mbB, par);
        #pragma unroll
        for (int i = 2; i < 5; i++) {
            const float4* cp = (const float4*)(mybuf + i * CAP_BYTES);
            float a = 0.f;
            #pragma unroll
            for (int j = 0; j < 9; j++) {
                const float4 x = cp[j * 32 + lane];
                const float4 w = ws[j * 32 + lane];
                a = fmaf(x.x, w.x, fmaf(x.y, w.y, fmaf(x.z, w.z, fmaf(x.w, w.w, a))));
            }
            acc[i] = a;
        }
        #pragma unroll
        for (int off = 16; off > 0; off >>= 1) {
            acc[2] += __shfl_xor_sync(0xffffffffu, acc[2], off);
            acc[3] += __shfl_xor_sync(0xffffffffu, acc[3], off);
            acc[4] += __shfl_xor_sync(0xffffffffu, acc[4], off);
        }
        __syncwarp();
        if (lane == 0 && more) {               // refill B with next element
            mbar_expect_tx(mbB, B_BYTES);
            bulk_load(buf_u + A_BYTES, nsrc + A_BYTES, B_BYTES, mbB);
        }

        // ---- Phase 2: routing (overlaps both in-flight refills) ----
        const float sumUh = acc[0] + acc[1] + acc[2] + acc[3] + acc[4];
        const float r0    = __fdividef(sumUh, d0);
        const float s0    = e0w * r0;
        const float s1    = e1w * r0;
        const float v0 = __fdividef(fabsf(s0) * s0, 1.f + s0 * s0);  // squash
        const float v1 = __fdividef(fabsf(s1) * s1, 1.f + s1 * s1);

        float mi[5];
        #pragma unroll
        for (int i = 0; i < 5; i++) {
            mi[i] = fmaf(v0, acc[i], base0);
            if (has1) mi[i] = fmaxf(mi[i], fmaf(v1, acc[i], base1));
        }
        #pragma unroll
        for (int off = 16; off > 0; off >>= 1) {
            #pragma unroll
            for (int i = 0; i < 5; i++)
                mi[i] = fmaxf(mi[i], __shfl_xor_sync(0xffffffffu, mi[i], off));
        }

        float e0i[5], e1i[5], di[5];
        #pragma unroll
        for (int i = 0; i < 5; i++) {
            e0i[i] = __expf(fmaf(v0, acc[i], base0) - mi[i]);
            e1i[i] = has1 ? __expf(fmaf(v1, acc[i], base1) - mi[i]) : 0.f;
            di[i]  = e0i[i] + e1i[i];
        }
        #pragma unroll
        for (int off = 16; off > 0; off >>= 1) {
            #pragma unroll
            for (int i = 0; i < 5; i++)
                di[i] += __shfl_xor_sync(0xffffffffu, di[i], off);
        }

        float t0 = 0.f, t1 = 0.f;
        #pragma unroll
        for (int i = 0; i < 5; i++) {
            const float r = __fdividef(acc[i], di[i]);
            t0 = fmaf(e0i[i], r, t0);
            t1 = fmaf(e1i[i], r, t1);
        }
        const float w0 = __fdividef(fabsf(t0) * t0, 1.f + t0 * t0);
        out[(size_t)n * OUT_CAP_N + o0] = w0;
        if (has1) {
            const float w1 = __fdividef(fabsf(t1) * t1, 1.f + t1 * t1);
            out[(size_t)n * OUT_CAP_N + o1] = w1;
        }
    }
}

extern "C" void kernel_launch(void* const* d_in, const int* in_sizes, int n_in,
                              void* d_out, int out_size) {
    const float4* u4   = (const float4*)d_in[0];  // (8192,5,128,3,3) f32
    const float4* w4   = (const float4*)d_in[1];  // (1,1152,1) f32
    const float*  bvec = (const float*) d_in[2];  // (55,1) f32
    float*        out  = (float*)d_out;           // (8192,55,1) f32

    static int smem_set = 0;
    if (!smem_set) {
        cudaFuncSetAttribute(digitcaps_kernel,
                             cudaFuncAttributeMaxDynamicSharedMemorySize, DYN_SMEM);
        smem_set = 1;
    }
    // 148 persistent CTAs; 8 warp-streams each, 2 sub-slot barriers per warp
    digitcaps_kernel<<<NCTA, 256, DYN_SMEM>>>(u4, w4, bvec, out);
}